// round 11
// baseline (speedup 1.0000x reference)
#include <cuda_runtime.h>
#include <cuda_bf16.h>
#include <cstdint>
#include <math.h>

#define NNODES 65536   // nodes per branch (B*S)
#define NB     8192    // graph blocks
#define SS     8       // nodes per block
#define EPB    64      // edges per block
#define DIN    512
#define DOUT   256

// ---- scratch (static device globals; no allocation allowed) ----
__device__ float g_pos_pool[NB * DOUT];
__device__ float g_neg_pool[NB * DOUT];
__device__ float g_anchor[NB * DOUT];
__device__ __nv_bfloat16 g_wt_hi[DOUT * DIN];   // W_gcn^T split-hi [256][512]
__device__ __nv_bfloat16 g_wt_lo[DOUT * DIN];   // W_gcn^T split-lo

// ======================= helpers =======================
__device__ __forceinline__ uint32_t smem_u32(const void* p) {
    uint32_t a;
    asm("{ .reg .u64 t; cvta.to.shared.u64 t, %1; cvt.u32.u64 %0, t; }"
        : "=r"(a) : "l"(p));
    return a;
}

#define LDSM_X4(r0, r1, r2, r3, addr) \
    asm volatile("ldmatrix.sync.aligned.m8n8.x4.shared.b16 {%0,%1,%2,%3}, [%4];" \
        : "=r"(r0), "=r"(r1), "=r"(r2), "=r"(r3) : "r"(addr))

#define MMA16816(d, a, b0, b1) \
    asm volatile("mma.sync.aligned.m16n8k16.row.col.f32.bf16.bf16.f32 " \
        "{%0,%1,%2,%3}, {%4,%5,%6,%7}, {%8,%9}, {%0,%1,%2,%3};" \
        : "+f"((d)[0]), "+f"((d)[1]), "+f"((d)[2]), "+f"((d)[3]) \
        : "r"((a)[0]), "r"((a)[1]), "r"((a)[2]), "r"((a)[3]), "r"(b0), "r"(b1))

__device__ __forceinline__ void split2(float x0, float x1, uint32_t& h, uint32_t& l) {
    __nv_bfloat16 h0 = __float2bfloat16(x0);
    __nv_bfloat16 h1 = __float2bfloat16(x1);
    __nv_bfloat16 l0 = __float2bfloat16(x0 - __bfloat162float(h0));
    __nv_bfloat16 l1 = __float2bfloat16(x1 - __bfloat162float(h1));
    __nv_bfloat162 hh = __halves2bfloat162(h0, h1);
    __nv_bfloat162 ll = __halves2bfloat162(l0, l1);
    h = *reinterpret_cast<uint32_t*>(&hh);
    l = *reinterpret_cast<uint32_t*>(&ll);
}

// ============ W_gcn split + transpose: [512][256] f32 -> [256][512] bf16 x2 ======
__global__ __launch_bounds__(256) void wsplit_kernel(const float* __restrict__ Wg)
{
    int idx = blockIdx.x * 256 + threadIdx.x;   // 131072 elems
    int k = idx >> 8;
    int n = idx & 255;
    float x = Wg[idx];
    __nv_bfloat16 h = __float2bfloat16(x);
    __nv_bfloat16 l = __float2bfloat16(x - __bfloat162float(h));
    g_wt_hi[(size_t)n * DIN + k] = h;
    g_wt_lo[(size_t)n * DIN + k] = l;
}

// ====== GEMM1 fused, 512 threads, double-buffered tiles + agg epilogue ======
// 16 warps, warp tile 32x64 (4m x 4n). Each CTA covers 16 whole graph blocks.
#define RPAD    80
#define HS      258                      // h row stride in floats
#define BUFB    61440
#define OFF_AHI 0
#define OFF_ALO 10240
#define OFF_BHI 20480
#define OFF_BLO 40960
#define OFF_H   0                        // unions with tile buffers (used after loop)
#define OFF_ADJ (128 * HS * 4)           // 132096
#define OFF_RED (OFF_ADJ + 16 * 64 * 4)  // 136192
#define SMEM_SZ (OFF_RED + 16 * 8 * 2 * 4)  // 137216

__global__ __launch_bounds__(512, 1) void gemm1_fused(
    const float* __restrict__ posx, const float* __restrict__ negx,
    const int* __restrict__ pos_src, const int* __restrict__ pos_dst,
    const float* __restrict__ pos_w,
    const int* __restrict__ neg_src, const int* __restrict__ neg_dst,
    const float* __restrict__ neg_w,
    const float* __restrict__ b_gcn, const float* __restrict__ prelu_a)
{
    extern __shared__ __align__(16) char smem[];
    float* sH   = (float*)(smem + OFF_H);
    float* sAdj = (float*)(smem + OFF_ADJ);
    float* sRed = (float*)(smem + OFF_RED);

    const int tid = threadIdx.x;
    const int wid = tid >> 5;
    const int lane = tid & 31;

    const int m0 = blockIdx.x * 128;
    const int is_pos = (m0 < NNODES);
    const int mloc = is_pos ? m0 : (m0 - NNODES);
    const int warp_m = (wid & 3) * 32;
    const int warp_n = (wid >> 2) * 64;

    const float* X = (is_pos ? posx : negx) + (size_t)mloc * DIN;
    const int*   src = is_pos ? pos_src : neg_src;
    const int*   dst = is_pos ? pos_dst : neg_dst;
    const float* ew  = is_pos ? pos_w   : neg_w;

    const uint32_t sb = smem_u32(smem);

    // ---- build 16 adjacency matrices early ----
    sAdj[tid] = 0.f;
    sAdj[tid + 512] = 0.f;
    __syncthreads();
    {
        const int eb = mloc * 8;             // 1024 edges for 16 blocks
        int2 s2 = *(const int2*)(src + eb + tid * 2);
        int2 d2 = *(const int2*)(dst + eb + tid * 2);
        float2 w2 = *(const float2*)(ew + eb + tid * 2);
        int blk = tid >> 5;                  // 2 edges/thread, 64 edges/blk
        atomicAdd(&sAdj[blk * 64 + (d2.x & 7) * 8 + (s2.x & 7)], w2.x);
        atomicAdd(&sAdj[blk * 64 + (d2.y & 7) * 8 + (s2.y & 7)], w2.y);
    }

    // ---- loader mappings (512 threads) ----
    const int a_lrow = tid >> 2;                // A: row t>>2, 8-float quarter
    const int a_part = (tid & 3) * 8;
    const float* aptr = X + (size_t)a_lrow * DIN + a_part;
    const uint32_t a_st = (uint32_t)a_lrow * RPAD + (uint32_t)a_part * 2;

    const int b_lrow = tid >> 1;                // B: row t>>1, 16-bf16 half
    const int b_part = (tid & 1) * 16;
    const __nv_bfloat16* bh_ptr = g_wt_hi + (size_t)b_lrow * DIN + b_part;
    const __nv_bfloat16* bl_ptr = g_wt_lo + (size_t)b_lrow * DIN + b_part;
    const uint32_t b_st = (uint32_t)b_lrow * RPAD + (uint32_t)b_part * 2;

    const int a_r  = lane & 15;
    const int a_cg = lane >> 4;
    const int b_t  = lane >> 3;
    const int b_r  = lane & 7;
    const int b_nn = ((b_t >> 1) << 3) + b_r;
    const int b_kk = (b_t & 1) << 3;

    float acc[2][8][4];
    #pragma unroll
    for (int i = 0; i < 2; i++)
        #pragma unroll
        for (int j = 0; j < 8; j++)
            #pragma unroll
            for (int q = 0; q < 4; q++) acc[i][j][q] = 0.f;

    // ---- prologue: chunk 0 -> regs -> buf0 ----
    float4 pA0 = *(const float4*)(aptr + 0);
    float4 pA1 = *(const float4*)(aptr + 4);
    uint4 pBh0 = *(const uint4*)((const char*)bh_ptr);
    uint4 pBh1 = *(const uint4*)((const char*)bh_ptr + 16);
    uint4 pBl0 = *(const uint4*)((const char*)bl_ptr);
    uint4 pBl1 = *(const uint4*)((const char*)bl_ptr + 16);
    {
        uint32_t h[4], l[4];
        split2(pA0.x, pA0.y, h[0], l[0]);
        split2(pA0.z, pA0.w, h[1], l[1]);
        split2(pA1.x, pA1.y, h[2], l[2]);
        split2(pA1.z, pA1.w, h[3], l[3]);
        *(uint4*)(smem + OFF_AHI + a_st) = make_uint4(h[0], h[1], h[2], h[3]);
        *(uint4*)(smem + OFF_ALO + a_st) = make_uint4(l[0], l[1], l[2], l[3]);
        *(uint4*)(smem + OFF_BHI + b_st)      = pBh0;
        *(uint4*)(smem + OFF_BHI + b_st + 16) = pBh1;
        *(uint4*)(smem + OFF_BLO + b_st)      = pBl0;
        *(uint4*)(smem + OFF_BLO + b_st + 16) = pBl1;
    }
    __syncthreads();

    for (int kt = 0; kt < DIN / 32; kt++) {
        const uint32_t cb = (uint32_t)(kt & 1) * BUFB;

        if (kt < DIN / 32 - 1) {
            const float* ap = aptr + (kt + 1) * 32;
            pA0 = *(const float4*)(ap + 0);
            pA1 = *(const float4*)(ap + 4);
            const char* bh = (const char*)(bh_ptr + (kt + 1) * 32);
            const char* bl = (const char*)(bl_ptr + (kt + 1) * 32);
            pBh0 = *(const uint4*)(bh);
            pBh1 = *(const uint4*)(bh + 16);
            pBl0 = *(const uint4*)(bl);
            pBl1 = *(const uint4*)(bl + 16);
        }

        const uint32_t ahi_b = sb + cb + OFF_AHI;
        const uint32_t alo_b = sb + cb + OFF_ALO;
        const uint32_t bhi_b = sb + cb + OFF_BHI;
        const uint32_t blo_b = sb + cb + OFF_BLO;
        #pragma unroll
        for (int k16 = 0; k16 < 32; k16 += 16) {
            uint32_t ahi[2][4], alo[2][4];
            #pragma unroll
            for (int mi = 0; mi < 2; mi++) {
                const uint32_t a_off = (uint32_t)(warp_m + mi * 16 + a_r) * RPAD
                                     + (uint32_t)(k16 + a_cg * 8) * 2;
                LDSM_X4(ahi[mi][0], ahi[mi][1], ahi[mi][2], ahi[mi][3], ahi_b + a_off);
                LDSM_X4(alo[mi][0], alo[mi][1], alo[mi][2], alo[mi][3], alo_b + a_off);
            }
            #pragma unroll
            for (int g = 0; g < 4; g++) {
                const uint32_t b_off = (uint32_t)(warp_n + g * 16 + b_nn) * RPAD
                                     + (uint32_t)(k16 + b_kk) * 2;
                uint32_t bh[4], bl[4];
                LDSM_X4(bh[0], bh[1], bh[2], bh[3], bhi_b + b_off);
                LDSM_X4(bl[0], bl[1], bl[2], bl[3], blo_b + b_off);
                #pragma unroll
                for (int mi = 0; mi < 2; mi++) {
                    MMA16816(acc[mi][g * 2 + 0], ahi[mi], bh[0], bh[1]);
                    MMA16816(acc[mi][g * 2 + 1], ahi[mi], bh[2], bh[3]);
                    MMA16816(acc[mi][g * 2 + 0], alo[mi], bh[0], bh[1]);
                    MMA16816(acc[mi][g * 2 + 1], alo[mi], bh[2], bh[3]);
                    MMA16816(acc[mi][g * 2 + 0], ahi[mi], bl[0], bl[1]);
                    MMA16816(acc[mi][g * 2 + 1], ahi[mi], bl[2], bl[3]);
                }
            }
        }

        if (kt < DIN / 32 - 1) {
            const uint32_t nb = (uint32_t)((kt + 1) & 1) * BUFB;
            uint32_t h[4], l[4];
            split2(pA0.x, pA0.y, h[0], l[0]);
            split2(pA0.z, pA0.w, h[1], l[1]);
            split2(pA1.x, pA1.y, h[2], l[2]);
            split2(pA1.z, pA1.w, h[3], l[3]);
            *(uint4*)(smem + nb + OFF_AHI + a_st) = make_uint4(h[0], h[1], h[2], h[3]);
            *(uint4*)(smem + nb + OFF_ALO + a_st) = make_uint4(l[0], l[1], l[2], l[3]);
            *(uint4*)(smem + nb + OFF_BHI + b_st)      = pBh0;
            *(uint4*)(smem + nb + OFF_BHI + b_st + 16) = pBh1;
            *(uint4*)(smem + nb + OFF_BLO + b_st)      = pBl0;
            *(uint4*)(smem + nb + OFF_BLO + b_st + 16) = pBl1;
        }
        __syncthreads();
    }

    // ---- epilogue: acc -> smem h (stride HS, conflict-free) ----
    const int er = lane >> 2;
    const int ec = (lane & 3) * 2;
    #pragma unroll
    for (int mi = 0; mi < 2; mi++) {
        #pragma unroll
        for (int nf = 0; nf < 8; nf++) {
            int row = warp_m + mi * 16 + er;
            int col = warp_n + nf * 8 + ec;
            *(float2*)&sH[(size_t)row * HS + col] =
                make_float2(acc[mi][nf][0], acc[mi][nf][1]);
            *(float2*)&sH[(size_t)(row + 8) * HS + col] =
                make_float2(acc[mi][nf][2], acc[mi][nf][3]);
        }
    }
    __syncthreads();

    // ---- agg + PReLU + pool/anchor; half h = tid>>8 does blocks h*8..h*8+7 ----
    const int half = tid >> 8;           // 0 or 1
    const int col  = tid & 255;
    const int hw   = wid & 7;            // warp index within half
    const float pa = prelu_a[0];
    const float bj = b_gcn[col];
    float poolv[8], anchv[8], vp[8], va[8];
    #pragma unroll
    for (int q = 0; q < 8; q++) {
        const int blk = half * 8 + q;
        float x[SS];
        #pragma unroll
        for (int s = 0; s < SS; s++) x[s] = sH[(size_t)(blk * 8 + s) * HS + col];
        float pool = 0.f, anchor = 0.f;
        #pragma unroll
        for (int r = 0; r < SS; r++) {
            float a = bj;
            #pragma unroll
            for (int s = 0; s < SS; s++)
                a = fmaf(sAdj[blk * 64 + r * 8 + s], x[s], a);
            float h = (a >= 0.f) ? a : pa * a;
            if (r < SS - 1) pool += h;
            else            anchor = h;
        }
        pool *= (1.0f / (float)(SS - 1));
        poolv[q] = pool;
        anchv[q] = anchor;
        float p2s = pool * pool, a2s = anchor * anchor;
        #pragma unroll
        for (int o = 16; o; o >>= 1) {
            p2s += __shfl_xor_sync(0xffffffffu, p2s, o);
            a2s += __shfl_xor_sync(0xffffffffu, a2s, o);
        }
        vp[q] = p2s;
        va[q] = a2s;
    }
    if (lane == 0) {
        #pragma unroll
        for (int q = 0; q < 8; q++) {
            const int blk = half * 8 + q;
            sRed[blk * 16 + hw * 2 + 0] = vp[q];
            sRed[blk * 16 + hw * 2 + 1] = va[q];
        }
    }
    __syncthreads();

    const int b0 = mloc / SS;
    #pragma unroll
    for (int q = 0; q < 8; q++) {
        const int blk = half * 8 + q;
        float sp = 0.f, sa = 0.f;
        #pragma unroll
        for (int w = 0; w < 8; w++) {
            sp += sRed[blk * 16 + w * 2 + 0];
            sa += sRed[blk * 16 + w * 2 + 1];
        }
        const float inp = 1.f / fmaxf(sqrtf(sp), 1e-12f);
        const float ina = 1.f / fmaxf(sqrtf(sa), 1e-12f);
        const size_t gi = (size_t)(b0 + blk) * DOUT + col;
        if (is_pos) {
            g_pos_pool[gi] = poolv[q] * inp;
            g_anchor[gi]   = anchv[q] * ina;
        } else {
            g_neg_pool[gi] = poolv[q] * inp;
        }
    }
}

// ============ out init: out[i] = b_bil for both score halves ============
__global__ __launch_bounds__(256) void out_init_kernel(
    const float* __restrict__ b_bil, float* __restrict__ out)
{
    int i = blockIdx.x * 256 + threadIdx.x;   // 2*NB elems
    out[i] = b_bil[0];
}

// ====== GEMM2+score fused: 128x64 tile (known-good reuse), K-SPLIT x2 ======
// T = anchor @ W_bil^T; score partials atomicAdd'ed (score linear in T).
#define G2_BM 128
#define G2_BN 64
#define G2_BK 16
#define G2_KSPLIT 2
#define G2_KRANGE (DOUT / G2_KSPLIT)   // 128

__global__ __launch_bounds__(256) void gemm2_fused(
    const float* __restrict__ Wb, float* __restrict__ out)
{
    __shared__ float As[G2_BK][G2_BM];
    __shared__ float Bs[G2_BK][G2_BN];

    const int tid = threadIdx.x;
    const int m0 = blockIdx.x * G2_BM;
    const int n0 = blockIdx.y * G2_BN;
    const int kbase = blockIdx.z * G2_KRANGE;

    const int ar = tid >> 2;              // 0..63 (A row base, +64 for 2nd)
    const int ac = (tid & 3) << 2;        // A k-chunk
    const int bn_ = tid >> 2;             // 0..63 (B n index)
    const int bkc = (tid & 3) << 2;       // B k-chunk
    const int ty = tid >> 4;              // 0..15 -> 8 rows
    const int tx = tid & 15;              // 0..15 -> 4 cols

    float acc[8][4];
    #pragma unroll
    for (int i = 0; i < 8; i++)
        #pragma unroll
        for (int j = 0; j < 4; j++) acc[i][j] = 0.f;

    for (int kk = 0; kk < G2_KRANGE; kk += G2_BK) {
        const int k0 = kbase + kk;
        #pragma unroll
        for (int c = 0; c < 2; c++) {
            int row = ar + c * 64;
            float4 v = *(const float4*)(&g_anchor[(size_t)(m0 + row) * DOUT + k0 + ac]);
            As[ac + 0][row] = v.x;
            As[ac + 1][row] = v.y;
            As[ac + 2][row] = v.z;
            As[ac + 3][row] = v.w;
        }
        {
            float4 v = *(const float4*)(Wb + (size_t)(n0 + bn_) * DOUT + k0 + bkc);
            Bs[bkc + 0][bn_] = v.x;
            Bs[bkc + 1][bn_] = v.y;
            Bs[bkc + 2][bn_] = v.z;
            Bs[bkc + 3][bn_] = v.w;
        }
        __syncthreads();

        #pragma unroll
        for (int k = 0; k < G2_BK; k++) {
            float a[8], bb[4];
            #pragma unroll
            for (int i = 0; i < 8; i++) a[i] = As[k][ty * 8 + i];
            #pragma unroll
            for (int j = 0; j < 4; j++) bb[j] = Bs[k][tx * 4 + j];
            #pragma unroll
            for (int i = 0; i < 8; i++)
                #pragma unroll
                for (int j = 0; j < 4; j++)
                    acc[i][j] = fmaf(a[i], bb[j], acc[i][j]);
        }
        __syncthreads();
    }

    // ---- fused score: dot partial-T tile with pool tiles, reduce over tx ----
    #pragma unroll
    for (int i = 0; i < 8; i++) {
        const int row = m0 + ty * 8 + i;
        float4 p4 = *(const float4*)(g_pos_pool + (size_t)row * DOUT + n0 + tx * 4);
        float4 n4 = *(const float4*)(g_neg_pool + (size_t)row * DOUT + n0 + tx * 4);
        float sp = acc[i][0] * p4.x + acc[i][1] * p4.y
                 + acc[i][2] * p4.z + acc[i][3] * p4.w;
        float sn = acc[i][0] * n4.x + acc[i][1] * n4.y
                 + acc[i][2] * n4.z + acc[i][3] * n4.w;
        // reduce across tx (lane = (ty&1)*16 + tx; xor<16 stays in the half)
        #pragma unroll
        for (int o = 8; o; o >>= 1) {
            sp += __shfl_xor_sync(0xffffffffu, sp, o);
            sn += __shfl_xor_sync(0xffffffffu, sn, o);
        }
        if (tx == 0) {
            atomicAdd(&out[row], sp);
            atomicAdd(&out[NB + row], sn);
        }
    }
}

extern "C" void kernel_launch(void* const* d_in, const int* in_sizes, int n_in,
                              void* d_out, int out_size)
{
    const float* pos_x   = (const float*)d_in[0];
    const float* neg_x   = (const float*)d_in[1];
    const int*   pos_src = (const int*)d_in[2];
    const int*   pos_dst = (const int*)d_in[3];
    const float* pos_w   = (const float*)d_in[4];
    const int*   neg_src = (const int*)d_in[5];
    const int*   neg_dst = (const int*)d_in[6];
    const float* neg_w   = (const float*)d_in[7];
    const float* W_gcn   = (const float*)d_in[8];
    const float* b_gcn   = (const float*)d_in[9];
    const float* prelu_a = (const float*)d_in[10];
    const float* W_bil   = (const float*)d_in[11];
    const float* b_bil   = (const float*)d_in[12];
    float* out = (float*)d_out;

    (void)in_sizes; (void)n_in; (void)out_size;

    cudaFuncSetAttribute(gemm1_fused, cudaFuncAttributeMaxDynamicSharedMemorySize,
                         SMEM_SZ);

    // 0) weight split + out init (independent of gemm1)
    wsplit_kernel<<<512, 256>>>(W_gcn);
    out_init_kernel<<<2 * NB / 256, 256>>>(b_bil, out);

    // 1) fused: xw GEMM + agg + PReLU + pool + anchor + L2 norm
    gemm1_fused<<<2 * NNODES / 128, 512, SMEM_SZ>>>(
        pos_x, neg_x, pos_src, pos_dst, pos_w,
        neg_src, neg_dst, neg_w, b_gcn, prelu_a);

    // 2) T tile GEMM (k-split) + fused bilinear scores (atomicAdd partials)
    gemm2_fused<<<dim3(NB / G2_BM, DOUT / G2_BN, G2_KSPLIT), 256>>>(W_bil, out);
}

// round 12
// speedup vs baseline: 1.0278x; 1.0278x over previous
#include <cuda_runtime.h>
#include <cuda_bf16.h>
#include <cstdint>
#include <math.h>

#define NNODES 65536   // nodes per branch (B*S)
#define NB     8192    // graph blocks
#define SS     8       // nodes per block
#define EPB    64      // edges per block
#define DIN    512
#define DOUT   256

// ---- scratch (static device globals; no allocation allowed) ----
__device__ float g_pos_pool[NB * DOUT];
__device__ float g_neg_pool[NB * DOUT];
__device__ float g_anchor[NB * DOUT];
__device__ __nv_bfloat16 g_wt_hi[DOUT * DIN];   // W_gcn^T split-hi [256][512]
__device__ __nv_bfloat16 g_wt_lo[DOUT * DIN];   // W_gcn^T split-lo
__device__ __nv_bfloat16 g_wb_hi[DOUT * DOUT];  // W_bil split-hi [256][256]
__device__ __nv_bfloat16 g_wb_lo[DOUT * DOUT];  // W_bil split-lo

// ======================= helpers =======================
__device__ __forceinline__ uint32_t smem_u32(const void* p) {
    uint32_t a;
    asm("{ .reg .u64 t; cvta.to.shared.u64 t, %1; cvt.u32.u64 %0, t; }"
        : "=r"(a) : "l"(p));
    return a;
}

#define LDSM_X4(r0, r1, r2, r3, addr) \
    asm volatile("ldmatrix.sync.aligned.m8n8.x4.shared.b16 {%0,%1,%2,%3}, [%4];" \
        : "=r"(r0), "=r"(r1), "=r"(r2), "=r"(r3) : "r"(addr))

#define MMA16816(d, a, b0, b1) \
    asm volatile("mma.sync.aligned.m16n8k16.row.col.f32.bf16.bf16.f32 " \
        "{%0,%1,%2,%3}, {%4,%5,%6,%7}, {%8,%9}, {%0,%1,%2,%3};" \
        : "+f"((d)[0]), "+f"((d)[1]), "+f"((d)[2]), "+f"((d)[3]) \
        : "r"((a)[0]), "r"((a)[1]), "r"((a)[2]), "r"((a)[3]), "r"(b0), "r"(b1))

__device__ __forceinline__ void split2(float x0, float x1, uint32_t& h, uint32_t& l) {
    __nv_bfloat16 h0 = __float2bfloat16(x0);
    __nv_bfloat16 h1 = __float2bfloat16(x1);
    __nv_bfloat16 l0 = __float2bfloat16(x0 - __bfloat162float(h0));
    __nv_bfloat16 l1 = __float2bfloat16(x1 - __bfloat162float(h1));
    __nv_bfloat162 hh = __halves2bfloat162(h0, h1);
    __nv_bfloat162 ll = __halves2bfloat162(l0, l1);
    h = *reinterpret_cast<uint32_t*>(&hh);
    l = *reinterpret_cast<uint32_t*>(&ll);
}

// ============ W_gcn split + transpose: [512][256] f32 -> [256][512] bf16 x2 ======
__global__ __launch_bounds__(256) void wsplit_kernel(const float* __restrict__ Wg)
{
    int idx = blockIdx.x * 256 + threadIdx.x;   // 131072 elems
    int k = idx >> 8;
    int n = idx & 255;
    float x = Wg[idx];
    __nv_bfloat16 h = __float2bfloat16(x);
    __nv_bfloat16 l = __float2bfloat16(x - __bfloat162float(h));
    g_wt_hi[(size_t)n * DIN + k] = h;
    g_wt_lo[(size_t)n * DIN + k] = l;
}

// ============ W_bil split (element-wise, no transpose) ============
__global__ __launch_bounds__(256) void wsplit_bil_kernel(const float* __restrict__ Wb)
{
    int idx = blockIdx.x * 256 + threadIdx.x;   // 65536 elems
    float x = Wb[idx];
    __nv_bfloat16 h = __float2bfloat16(x);
    __nv_bfloat16 l = __float2bfloat16(x - __bfloat162float(h));
    g_wb_hi[idx] = h;
    g_wb_lo[idx] = l;
}

// ============ out init: out[i] = b_bil for both score halves ============
__global__ __launch_bounds__(256) void out_init_kernel(
    const float* __restrict__ b_bil, float* __restrict__ out)
{
    int i = blockIdx.x * 256 + threadIdx.x;   // 2*NB elems
    out[i] = b_bil[0];
}

// ====== GEMM1 fused, 512 threads, double-buffered tiles + agg epilogue ======
#define RPAD    80
#define HS      258
#define BUFB    61440
#define OFF_AHI 0
#define OFF_ALO 10240
#define OFF_BHI 20480
#define OFF_BLO 40960
#define OFF_H   0
#define OFF_ADJ (128 * HS * 4)           // 132096
#define OFF_RED (OFF_ADJ + 16 * 64 * 4)  // 136192
#define SMEM_SZ (OFF_RED + 16 * 8 * 2 * 4)  // 137216

__global__ __launch_bounds__(512, 1) void gemm1_fused(
    const float* __restrict__ posx, const float* __restrict__ negx,
    const int* __restrict__ pos_src, const int* __restrict__ pos_dst,
    const float* __restrict__ pos_w,
    const int* __restrict__ neg_src, const int* __restrict__ neg_dst,
    const float* __restrict__ neg_w,
    const float* __restrict__ b_gcn, const float* __restrict__ prelu_a)
{
    extern __shared__ __align__(16) char smem[];
    float* sH   = (float*)(smem + OFF_H);
    float* sAdj = (float*)(smem + OFF_ADJ);
    float* sRed = (float*)(smem + OFF_RED);

    const int tid = threadIdx.x;
    const int wid = tid >> 5;
    const int lane = tid & 31;

    const int m0 = blockIdx.x * 128;
    const int is_pos = (m0 < NNODES);
    const int mloc = is_pos ? m0 : (m0 - NNODES);
    const int warp_m = (wid & 3) * 32;
    const int warp_n = (wid >> 2) * 64;

    const float* X = (is_pos ? posx : negx) + (size_t)mloc * DIN;
    const int*   src = is_pos ? pos_src : neg_src;
    const int*   dst = is_pos ? pos_dst : neg_dst;
    const float* ew  = is_pos ? pos_w   : neg_w;

    const uint32_t sb = smem_u32(smem);

    // ---- build 16 adjacency matrices early ----
    sAdj[tid] = 0.f;
    sAdj[tid + 512] = 0.f;
    __syncthreads();
    {
        const int eb = mloc * 8;
        int2 s2 = *(const int2*)(src + eb + tid * 2);
        int2 d2 = *(const int2*)(dst + eb + tid * 2);
        float2 w2 = *(const float2*)(ew + eb + tid * 2);
        int blk = tid >> 5;
        atomicAdd(&sAdj[blk * 64 + (d2.x & 7) * 8 + (s2.x & 7)], w2.x);
        atomicAdd(&sAdj[blk * 64 + (d2.y & 7) * 8 + (s2.y & 7)], w2.y);
    }

    const int a_lrow = tid >> 2;
    const int a_part = (tid & 3) * 8;
    const float* aptr = X + (size_t)a_lrow * DIN + a_part;
    const uint32_t a_st = (uint32_t)a_lrow * RPAD + (uint32_t)a_part * 2;

    const int b_lrow = tid >> 1;
    const int b_part = (tid & 1) * 16;
    const __nv_bfloat16* bh_ptr = g_wt_hi + (size_t)b_lrow * DIN + b_part;
    const __nv_bfloat16* bl_ptr = g_wt_lo + (size_t)b_lrow * DIN + b_part;
    const uint32_t b_st = (uint32_t)b_lrow * RPAD + (uint32_t)b_part * 2;

    const int a_r  = lane & 15;
    const int a_cg = lane >> 4;
    const int b_t  = lane >> 3;
    const int b_r  = lane & 7;
    const int b_nn = ((b_t >> 1) << 3) + b_r;
    const int b_kk = (b_t & 1) << 3;

    float acc[2][8][4];
    #pragma unroll
    for (int i = 0; i < 2; i++)
        #pragma unroll
        for (int j = 0; j < 8; j++)
            #pragma unroll
            for (int q = 0; q < 4; q++) acc[i][j][q] = 0.f;

    float4 pA0 = *(const float4*)(aptr + 0);
    float4 pA1 = *(const float4*)(aptr + 4);
    uint4 pBh0 = *(const uint4*)((const char*)bh_ptr);
    uint4 pBh1 = *(const uint4*)((const char*)bh_ptr + 16);
    uint4 pBl0 = *(const uint4*)((const char*)bl_ptr);
    uint4 pBl1 = *(const uint4*)((const char*)bl_ptr + 16);
    {
        uint32_t h[4], l[4];
        split2(pA0.x, pA0.y, h[0], l[0]);
        split2(pA0.z, pA0.w, h[1], l[1]);
        split2(pA1.x, pA1.y, h[2], l[2]);
        split2(pA1.z, pA1.w, h[3], l[3]);
        *(uint4*)(smem + OFF_AHI + a_st) = make_uint4(h[0], h[1], h[2], h[3]);
        *(uint4*)(smem + OFF_ALO + a_st) = make_uint4(l[0], l[1], l[2], l[3]);
        *(uint4*)(smem + OFF_BHI + b_st)      = pBh0;
        *(uint4*)(smem + OFF_BHI + b_st + 16) = pBh1;
        *(uint4*)(smem + OFF_BLO + b_st)      = pBl0;
        *(uint4*)(smem + OFF_BLO + b_st + 16) = pBl1;
    }
    __syncthreads();

    for (int kt = 0; kt < DIN / 32; kt++) {
        const uint32_t cb = (uint32_t)(kt & 1) * BUFB;

        if (kt < DIN / 32 - 1) {
            const float* ap = aptr + (kt + 1) * 32;
            pA0 = *(const float4*)(ap + 0);
            pA1 = *(const float4*)(ap + 4);
            const char* bh = (const char*)(bh_ptr + (kt + 1) * 32);
            const char* bl = (const char*)(bl_ptr + (kt + 1) * 32);
            pBh0 = *(const uint4*)(bh);
            pBh1 = *(const uint4*)(bh + 16);
            pBl0 = *(const uint4*)(bl);
            pBl1 = *(const uint4*)(bl + 16);
        }

        const uint32_t ahi_b = sb + cb + OFF_AHI;
        const uint32_t alo_b = sb + cb + OFF_ALO;
        const uint32_t bhi_b = sb + cb + OFF_BHI;
        const uint32_t blo_b = sb + cb + OFF_BLO;
        #pragma unroll
        for (int k16 = 0; k16 < 32; k16 += 16) {
            uint32_t ahi[2][4], alo[2][4];
            #pragma unroll
            for (int mi = 0; mi < 2; mi++) {
                const uint32_t a_off = (uint32_t)(warp_m + mi * 16 + a_r) * RPAD
                                     + (uint32_t)(k16 + a_cg * 8) * 2;
                LDSM_X4(ahi[mi][0], ahi[mi][1], ahi[mi][2], ahi[mi][3], ahi_b + a_off);
                LDSM_X4(alo[mi][0], alo[mi][1], alo[mi][2], alo[mi][3], alo_b + a_off);
            }
            #pragma unroll
            for (int g = 0; g < 4; g++) {
                const uint32_t b_off = (uint32_t)(warp_n + g * 16 + b_nn) * RPAD
                                     + (uint32_t)(k16 + b_kk) * 2;
                uint32_t bh[4], bl[4];
                LDSM_X4(bh[0], bh[1], bh[2], bh[3], bhi_b + b_off);
                LDSM_X4(bl[0], bl[1], bl[2], bl[3], blo_b + b_off);
                #pragma unroll
                for (int mi = 0; mi < 2; mi++) {
                    MMA16816(acc[mi][g * 2 + 0], ahi[mi], bh[0], bh[1]);
                    MMA16816(acc[mi][g * 2 + 1], ahi[mi], bh[2], bh[3]);
                    MMA16816(acc[mi][g * 2 + 0], alo[mi], bh[0], bh[1]);
                    MMA16816(acc[mi][g * 2 + 1], alo[mi], bh[2], bh[3]);
                    MMA16816(acc[mi][g * 2 + 0], ahi[mi], bl[0], bl[1]);
                    MMA16816(acc[mi][g * 2 + 1], ahi[mi], bl[2], bl[3]);
                }
            }
        }

        if (kt < DIN / 32 - 1) {
            const uint32_t nb = (uint32_t)((kt + 1) & 1) * BUFB;
            uint32_t h[4], l[4];
            split2(pA0.x, pA0.y, h[0], l[0]);
            split2(pA0.z, pA0.w, h[1], l[1]);
            split2(pA1.x, pA1.y, h[2], l[2]);
            split2(pA1.z, pA1.w, h[3], l[3]);
            *(uint4*)(smem + nb + OFF_AHI + a_st) = make_uint4(h[0], h[1], h[2], h[3]);
            *(uint4*)(smem + nb + OFF_ALO + a_st) = make_uint4(l[0], l[1], l[2], l[3]);
            *(uint4*)(smem + nb + OFF_BHI + b_st)      = pBh0;
            *(uint4*)(smem + nb + OFF_BHI + b_st + 16) = pBh1;
            *(uint4*)(smem + nb + OFF_BLO + b_st)      = pBl0;
            *(uint4*)(smem + nb + OFF_BLO + b_st + 16) = pBl1;
        }
        __syncthreads();
    }

    // ---- epilogue: acc -> smem h (stride HS) ----
    const int er = lane >> 2;
    const int ec = (lane & 3) * 2;
    #pragma unroll
    for (int mi = 0; mi < 2; mi++) {
        #pragma unroll
        for (int nf = 0; nf < 8; nf++) {
            int row = warp_m + mi * 16 + er;
            int col = warp_n + nf * 8 + ec;
            *(float2*)&sH[(size_t)row * HS + col] =
                make_float2(acc[mi][nf][0], acc[mi][nf][1]);
            *(float2*)&sH[(size_t)(row + 8) * HS + col] =
                make_float2(acc[mi][nf][2], acc[mi][nf][3]);
        }
    }
    __syncthreads();

    // ---- agg + PReLU + pool/anchor ----
    const int half = tid >> 8;
    const int col  = tid & 255;
    const int hw   = wid & 7;
    const float pa = prelu_a[0];
    const float bj = b_gcn[col];
    float poolv[8], anchv[8], vp[8], va[8];
    #pragma unroll
    for (int q = 0; q < 8; q++) {
        const int blk = half * 8 + q;
        float x[SS];
        #pragma unroll
        for (int s = 0; s < SS; s++) x[s] = sH[(size_t)(blk * 8 + s) * HS + col];
        float pool = 0.f, anchor = 0.f;
        #pragma unroll
        for (int r = 0; r < SS; r++) {
            float a = bj;
            #pragma unroll
            for (int s = 0; s < SS; s++)
                a = fmaf(sAdj[blk * 64 + r * 8 + s], x[s], a);
            float h = (a >= 0.f) ? a : pa * a;
            if (r < SS - 1) pool += h;
            else            anchor = h;
        }
        pool *= (1.0f / (float)(SS - 1));
        poolv[q] = pool;
        anchv[q] = anchor;
        float p2s = pool * pool, a2s = anchor * anchor;
        #pragma unroll
        for (int o = 16; o; o >>= 1) {
            p2s += __shfl_xor_sync(0xffffffffu, p2s, o);
            a2s += __shfl_xor_sync(0xffffffffu, a2s, o);
        }
        vp[q] = p2s;
        va[q] = a2s;
    }
    if (lane == 0) {
        #pragma unroll
        for (int q = 0; q < 8; q++) {
            const int blk = half * 8 + q;
            sRed[blk * 16 + hw * 2 + 0] = vp[q];
            sRed[blk * 16 + hw * 2 + 1] = va[q];
        }
    }
    __syncthreads();

    const int b0 = mloc / SS;
    #pragma unroll
    for (int q = 0; q < 8; q++) {
        const int blk = half * 8 + q;
        float sp = 0.f, sa = 0.f;
        #pragma unroll
        for (int w = 0; w < 8; w++) {
            sp += sRed[blk * 16 + w * 2 + 0];
            sa += sRed[blk * 16 + w * 2 + 1];
        }
        const float inp = 1.f / fmaxf(sqrtf(sp), 1e-12f);
        const float ina = 1.f / fmaxf(sqrtf(sa), 1e-12f);
        const size_t gi = (size_t)(b0 + blk) * DOUT + col;
        if (is_pos) {
            g_pos_pool[gi] = poolv[q] * inp;
            g_anchor[gi]   = anchv[q] * ina;
        } else {
            g_neg_pool[gi] = poolv[q] * inp;
        }
    }
}

// ====== GEMM2 via bf16 3-term mma + fused score, single wave (128 CTAs) ======
// T-tile = anchor[128 rows] @ W_bil^T over n-half 128, K=256. 256 threads,
// 8 warps (4m x 2n), warp tile 32x64. Epilogue: T -> smem, dot with pools,
// atomicAdd partial scores (out pre-initialized to b_bil).
#define TS 132    // T smem row stride (floats)
#define G2_AHI 0
#define G2_ALO 10240
#define G2_BHI 20480
#define G2_BLO 30720
#define G2_SMEM (128 * TS * 4)   // 67584; unions operand tiles (<= 40960)

__global__ __launch_bounds__(256, 1) void gemm2_mma(float* __restrict__ out)
{
    extern __shared__ __align__(16) char smem[];
    float* sT = (float*)smem;

    const int tid = threadIdx.x;
    const int wid = tid >> 5;
    const int lane = tid & 31;

    const int m0 = blockIdx.x * 128;
    const int n0 = blockIdx.y * 128;
    const int warp_m = (wid & 3) * 32;
    const int warp_n = (wid >> 2) * 64;

    const uint32_t sb = smem_u32(smem);

    // loaders: A anchor rows (fp32, split on the fly), 128 rows x 32 floats
    const int a_lrow = tid >> 1;                 // 0..127
    const int a_part = (tid & 1) * 16;           // 16 floats per thread
    const float* aptr = g_anchor + (size_t)(m0 + a_lrow) * DOUT + a_part;
    const uint32_t a_st = (uint32_t)a_lrow * RPAD + (uint32_t)a_part * 2;

    // B: W_bil rows n0+row (pre-split), 128 rows x 32 bf16
    const int b_lrow = tid >> 1;
    const int b_part = (tid & 1) * 16;
    const __nv_bfloat16* bh_ptr = g_wb_hi + (size_t)(n0 + b_lrow) * DOUT + b_part;
    const __nv_bfloat16* bl_ptr = g_wb_lo + (size_t)(n0 + b_lrow) * DOUT + b_part;
    const uint32_t b_st = (uint32_t)b_lrow * RPAD + (uint32_t)b_part * 2;

    const int a_r  = lane & 15;
    const int a_cg = lane >> 4;
    const int b_t  = lane >> 3;
    const int b_r  = lane & 7;
    const int b_nn = ((b_t >> 1) << 3) + b_r;
    const int b_kk = (b_t & 1) << 3;

    float acc[2][8][4];
    #pragma unroll
    for (int i = 0; i < 2; i++)
        #pragma unroll
        for (int j = 0; j < 8; j++)
            #pragma unroll
            for (int q = 0; q < 4; q++) acc[i][j][q] = 0.f;

    for (int kt = 0; kt < DOUT / 32; kt++) {
        const int k0 = kt * 32;
        {
            const float* ap = aptr + k0;
            float4 v0 = *(const float4*)(ap + 0);
            float4 v1 = *(const float4*)(ap + 4);
            float4 v2 = *(const float4*)(ap + 8);
            float4 v3 = *(const float4*)(ap + 12);
            uint32_t h[8], l[8];
            split2(v0.x, v0.y, h[0], l[0]);
            split2(v0.z, v0.w, h[1], l[1]);
            split2(v1.x, v1.y, h[2], l[2]);
            split2(v1.z, v1.w, h[3], l[3]);
            split2(v2.x, v2.y, h[4], l[4]);
            split2(v2.z, v2.w, h[5], l[5]);
            split2(v3.x, v3.y, h[6], l[6]);
            split2(v3.z, v3.w, h[7], l[7]);
            *(uint4*)(smem + G2_AHI + a_st)      = make_uint4(h[0], h[1], h[2], h[3]);
            *(uint4*)(smem + G2_AHI + a_st + 16) = make_uint4(h[4], h[5], h[6], h[7]);
            *(uint4*)(smem + G2_ALO + a_st)      = make_uint4(l[0], l[1], l[2], l[3]);
            *(uint4*)(smem + G2_ALO + a_st + 16) = make_uint4(l[4], l[5], l[6], l[7]);
        }
        {
            const char* bh = (const char*)(bh_ptr + k0);
            const char* bl = (const char*)(bl_ptr + k0);
            uint4 h0 = *(const uint4*)(bh);
            uint4 h1 = *(const uint4*)(bh + 16);
            uint4 l0 = *(const uint4*)(bl);
            uint4 l1 = *(const uint4*)(bl + 16);
            *(uint4*)(smem + G2_BHI + b_st)      = h0;
            *(uint4*)(smem + G2_BHI + b_st + 16) = h1;
            *(uint4*)(smem + G2_BLO + b_st)      = l0;
            *(uint4*)(smem + G2_BLO + b_st + 16) = l1;
        }
        __syncthreads();

        #pragma unroll
        for (int k16 = 0; k16 < 32; k16 += 16) {
            uint32_t ahi[2][4], alo[2][4];
            #pragma unroll
            for (int mi = 0; mi < 2; mi++) {
                const uint32_t a_off = (uint32_t)(warp_m + mi * 16 + a_r) * RPAD
                                     + (uint32_t)(k16 + a_cg * 8) * 2;
                LDSM_X4(ahi[mi][0], ahi[mi][1], ahi[mi][2], ahi[mi][3], sb + G2_AHI + a_off);
                LDSM_X4(alo[mi][0], alo[mi][1], alo[mi][2], alo[mi][3], sb + G2_ALO + a_off);
            }
            #pragma unroll
            for (int g = 0; g < 4; g++) {
                const uint32_t b_off = (uint32_t)(warp_n + g * 16 + b_nn) * RPAD
                                     + (uint32_t)(k16 + b_kk) * 2;
                uint32_t bh[4], bl[4];
                LDSM_X4(bh[0], bh[1], bh[2], bh[3], sb + G2_BHI + b_off);
                LDSM_X4(bl[0], bl[1], bl[2], bl[3], sb + G2_BLO + b_off);
                #pragma unroll
                for (int mi = 0; mi < 2; mi++) {
                    MMA16816(acc[mi][g * 2 + 0], ahi[mi], bh[0], bh[1]);
                    MMA16816(acc[mi][g * 2 + 1], ahi[mi], bh[2], bh[3]);
                    MMA16816(acc[mi][g * 2 + 0], alo[mi], bh[0], bh[1]);
                    MMA16816(acc[mi][g * 2 + 1], alo[mi], bh[2], bh[3]);
                    MMA16816(acc[mi][g * 2 + 0], ahi[mi], bl[0], bl[1]);
                    MMA16816(acc[mi][g * 2 + 1], ahi[mi], bl[2], bl[3]);
                }
            }
        }
        __syncthreads();
    }

    // ---- T tile -> smem ----
    const int er = lane >> 2;
    const int ec = (lane & 3) * 2;
    #pragma unroll
    for (int mi = 0; mi < 2; mi++) {
        #pragma unroll
        for (int nf = 0; nf < 8; nf++) {
            int row = warp_m + mi * 16 + er;
            int col = warp_n + nf * 8 + ec;
            *(float2*)&sT[(size_t)row * TS + col] =
                make_float2(acc[mi][nf][0], acc[mi][nf][1]);
            *(float2*)&sT[(size_t)(row + 8) * TS + col] =
                make_float2(acc[mi][nf][2], acc[mi][nf][3]);
        }
    }
    __syncthreads();

    // ---- fused score: warp w handles rows w*16..w*16+15 ----
    #pragma unroll
    for (int rr = 0; rr < 16; rr++) {
        const int r = wid * 16 + rr;
        const int grow = m0 + r;
        const float* pp = g_pos_pool + (size_t)grow * DOUT + n0;
        const float* np = g_neg_pool + (size_t)grow * DOUT + n0;
        float sp = 0.f, sn = 0.f;
        #pragma unroll
        for (int q = 0; q < 4; q++) {
            float t = sT[(size_t)r * TS + lane + q * 32];
            sp = fmaf(t, pp[lane + q * 32], sp);
            sn = fmaf(t, np[lane + q * 32], sn);
        }
        #pragma unroll
        for (int o = 16; o; o >>= 1) {
            sp += __shfl_xor_sync(0xffffffffu, sp, o);
            sn += __shfl_xor_sync(0xffffffffu, sn, o);
        }
        if (lane == 0) {
            atomicAdd(&out[grow], sp);
            atomicAdd(&out[NB + grow], sn);
        }
    }
}

extern "C" void kernel_launch(void* const* d_in, const int* in_sizes, int n_in,
                              void* d_out, int out_size)
{
    const float* pos_x   = (const float*)d_in[0];
    const float* neg_x   = (const float*)d_in[1];
    const int*   pos_src = (const int*)d_in[2];
    const int*   pos_dst = (const int*)d_in[3];
    const float* pos_w   = (const float*)d_in[4];
    const int*   neg_src = (const int*)d_in[5];
    const int*   neg_dst = (const int*)d_in[6];
    const float* neg_w   = (const float*)d_in[7];
    const float* W_gcn   = (const float*)d_in[8];
    const float* b_gcn   = (const float*)d_in[9];
    const float* prelu_a = (const float*)d_in[10];
    const float* W_bil   = (const float*)d_in[11];
    const float* b_bil   = (const float*)d_in[12];
    float* out = (float*)d_out;

    (void)in_sizes; (void)n_in; (void)out_size;

    cudaFuncSetAttribute(gemm1_fused, cudaFuncAttributeMaxDynamicSharedMemorySize,
                         SMEM_SZ);
    cudaFuncSetAttribute(gemm2_mma, cudaFuncAttributeMaxDynamicSharedMemorySize,
                         G2_SMEM);

    // 0) weight splits + out init
    wsplit_kernel<<<512, 256>>>(W_gcn);
    wsplit_bil_kernel<<<256, 256>>>(W_bil);
    out_init_kernel<<<2 * NB / 256, 256>>>(b_bil, out);

    // 1) fused: xw GEMM + agg + PReLU + pool + anchor + L2 norm
    gemm1_fused<<<2 * NNODES / 128, 512, SMEM_SZ>>>(
        pos_x, neg_x, pos_src, pos_dst, pos_w,
        neg_src, neg_dst, neg_w, b_gcn, prelu_a);

    // 2) T = anchor @ W_bil^T (bf16 3-term mma) + fused scores, single wave
    gemm2_mma<<<dim3(NB / 128, DOUT / 128), 256, G2_SMEM>>>(out);
}

// round 13
// speedup vs baseline: 1.0307x; 1.0027x over previous
#include <cuda_runtime.h>
#include <cuda_bf16.h>
#include <cstdint>
#include <math.h>

#define NNODES 65536   // nodes per branch (B*S)
#define NB     8192    // graph blocks
#define SS     8       // nodes per block
#define EPB    64      // edges per block
#define DIN    512
#define DOUT   256

// ---- scratch (static device globals; no allocation allowed) ----
__device__ float g_pos_pool[NB * DOUT];
__device__ float g_neg_pool[NB * DOUT];
__device__ float g_anchor[NB * DOUT];
__device__ __nv_bfloat16 g_wt_hi[DOUT * DIN];   // W_gcn^T split-hi [256][512]
__device__ __nv_bfloat16 g_wt_lo[DOUT * DIN];   // W_gcn^T split-lo
__device__ __nv_bfloat16 g_wb_hi[DOUT * DOUT];  // W_bil split-hi [256][256]
__device__ __nv_bfloat16 g_wb_lo[DOUT * DOUT];  // W_bil split-lo

// ======================= helpers =======================
__device__ __forceinline__ uint32_t smem_u32(const void* p) {
    uint32_t a;
    asm("{ .reg .u64 t; cvta.to.shared.u64 t, %1; cvt.u32.u64 %0, t; }"
        : "=r"(a) : "l"(p));
    return a;
}

#define LDSM_X4(r0, r1, r2, r3, addr) \
    asm volatile("ldmatrix.sync.aligned.m8n8.x4.shared.b16 {%0,%1,%2,%3}, [%4];" \
        : "=r"(r0), "=r"(r1), "=r"(r2), "=r"(r3) : "r"(addr))

#define MMA16816(d, a, b0, b1) \
    asm volatile("mma.sync.aligned.m16n8k16.row.col.f32.bf16.bf16.f32 " \
        "{%0,%1,%2,%3}, {%4,%5,%6,%7}, {%8,%9}, {%0,%1,%2,%3};" \
        : "+f"((d)[0]), "+f"((d)[1]), "+f"((d)[2]), "+f"((d)[3]) \
        : "r"((a)[0]), "r"((a)[1]), "r"((a)[2]), "r"((a)[3]), "r"(b0), "r"(b1))

__device__ __forceinline__ void split2(float x0, float x1, uint32_t& h, uint32_t& l) {
    __nv_bfloat16 h0 = __float2bfloat16(x0);
    __nv_bfloat16 h1 = __float2bfloat16(x1);
    __nv_bfloat16 l0 = __float2bfloat16(x0 - __bfloat162float(h0));
    __nv_bfloat16 l1 = __float2bfloat16(x1 - __bfloat162float(h1));
    __nv_bfloat162 hh = __halves2bfloat162(h0, h1);
    __nv_bfloat162 ll = __halves2bfloat162(l0, l1);
    h = *reinterpret_cast<uint32_t*>(&hh);
    l = *reinterpret_cast<uint32_t*>(&ll);
}

// ============ W_gcn split + transpose: [512][256] f32 -> [256][512] bf16 x2 ======
__global__ __launch_bounds__(256) void wsplit_kernel(const float* __restrict__ Wg)
{
    int idx = blockIdx.x * 256 + threadIdx.x;   // 131072 elems
    int k = idx >> 8;
    int n = idx & 255;
    float x = Wg[idx];
    __nv_bfloat16 h = __float2bfloat16(x);
    __nv_bfloat16 l = __float2bfloat16(x - __bfloat162float(h));
    g_wt_hi[(size_t)n * DIN + k] = h;
    g_wt_lo[(size_t)n * DIN + k] = l;
}

// ============ W_bil split (element-wise, no transpose) ============
__global__ __launch_bounds__(256) void wsplit_bil_kernel(const float* __restrict__ Wb)
{
    int idx = blockIdx.x * 256 + threadIdx.x;   // 65536 elems
    float x = Wb[idx];
    __nv_bfloat16 h = __float2bfloat16(x);
    __nv_bfloat16 l = __float2bfloat16(x - __bfloat162float(h));
    g_wb_hi[idx] = h;
    g_wb_lo[idx] = l;
}

// ============ out init: out[i] = b_bil for both score halves ============
__global__ __launch_bounds__(256) void out_init_kernel(
    const float* __restrict__ b_bil, float* __restrict__ out)
{
    int i = blockIdx.x * 256 + threadIdx.x;   // 2*NB elems
    out[i] = b_bil[0];
}

// ====== GEMM1 fused, 512 threads, double-buffered tiles + agg epilogue ======
#define RPAD    80
#define HS      258
#define BUFB    61440
#define OFF_AHI 0
#define OFF_ALO 10240
#define OFF_BHI 20480
#define OFF_BLO 40960
#define OFF_H   0
#define OFF_ADJ (128 * HS * 4)           // 132096
#define OFF_RED (OFF_ADJ + 16 * 64 * 4)  // 136192
#define SMEM_SZ (OFF_RED + 16 * 8 * 2 * 4)  // 137216

__global__ __launch_bounds__(512, 1) void gemm1_fused(
    const float* __restrict__ posx, const float* __restrict__ negx,
    const int* __restrict__ pos_src, const int* __restrict__ pos_dst,
    const float* __restrict__ pos_w,
    const int* __restrict__ neg_src, const int* __restrict__ neg_dst,
    const float* __restrict__ neg_w,
    const float* __restrict__ b_gcn, const float* __restrict__ prelu_a)
{
    extern __shared__ __align__(16) char smem[];
    float* sH   = (float*)(smem + OFF_H);
    float* sAdj = (float*)(smem + OFF_ADJ);
    float* sRed = (float*)(smem + OFF_RED);

    const int tid = threadIdx.x;
    const int wid = tid >> 5;
    const int lane = tid & 31;

    const int m0 = blockIdx.x * 128;
    const int is_pos = (m0 < NNODES);
    const int mloc = is_pos ? m0 : (m0 - NNODES);
    const int warp_m = (wid & 3) * 32;
    const int warp_n = (wid >> 2) * 64;

    const float* X = (is_pos ? posx : negx) + (size_t)mloc * DIN;
    const int*   src = is_pos ? pos_src : neg_src;
    const int*   dst = is_pos ? pos_dst : neg_dst;
    const float* ew  = is_pos ? pos_w   : neg_w;

    const uint32_t sb = smem_u32(smem);

    // ---- build 16 adjacency matrices early ----
    sAdj[tid] = 0.f;
    sAdj[tid + 512] = 0.f;
    __syncthreads();
    {
        const int eb = mloc * 8;
        int2 s2 = *(const int2*)(src + eb + tid * 2);
        int2 d2 = *(const int2*)(dst + eb + tid * 2);
        float2 w2 = *(const float2*)(ew + eb + tid * 2);
        int blk = tid >> 5;
        atomicAdd(&sAdj[blk * 64 + (d2.x & 7) * 8 + (s2.x & 7)], w2.x);
        atomicAdd(&sAdj[blk * 64 + (d2.y & 7) * 8 + (s2.y & 7)], w2.y);
    }

    const int a_lrow = tid >> 2;
    const int a_part = (tid & 3) * 8;
    const float* aptr = X + (size_t)a_lrow * DIN + a_part;
    const uint32_t a_st = (uint32_t)a_lrow * RPAD + (uint32_t)a_part * 2;

    const int b_lrow = tid >> 1;
    const int b_part = (tid & 1) * 16;
    const __nv_bfloat16* bh_ptr = g_wt_hi + (size_t)b_lrow * DIN + b_part;
    const __nv_bfloat16* bl_ptr = g_wt_lo + (size_t)b_lrow * DIN + b_part;
    const uint32_t b_st = (uint32_t)b_lrow * RPAD + (uint32_t)b_part * 2;

    const int a_r  = lane & 15;
    const int a_cg = lane >> 4;
    const int b_t  = lane >> 3;
    const int b_r  = lane & 7;
    const int b_nn = ((b_t >> 1) << 3) + b_r;
    const int b_kk = (b_t & 1) << 3;

    float acc[2][8][4];
    #pragma unroll
    for (int i = 0; i < 2; i++)
        #pragma unroll
        for (int j = 0; j < 8; j++)
            #pragma unroll
            for (int q = 0; q < 4; q++) acc[i][j][q] = 0.f;

    float4 pA0 = *(const float4*)(aptr + 0);
    float4 pA1 = *(const float4*)(aptr + 4);
    uint4 pBh0 = *(const uint4*)((const char*)bh_ptr);
    uint4 pBh1 = *(const uint4*)((const char*)bh_ptr + 16);
    uint4 pBl0 = *(const uint4*)((const char*)bl_ptr);
    uint4 pBl1 = *(const uint4*)((const char*)bl_ptr + 16);
    {
        uint32_t h[4], l[4];
        split2(pA0.x, pA0.y, h[0], l[0]);
        split2(pA0.z, pA0.w, h[1], l[1]);
        split2(pA1.x, pA1.y, h[2], l[2]);
        split2(pA1.z, pA1.w, h[3], l[3]);
        *(uint4*)(smem + OFF_AHI + a_st) = make_uint4(h[0], h[1], h[2], h[3]);
        *(uint4*)(smem + OFF_ALO + a_st) = make_uint4(l[0], l[1], l[2], l[3]);
        *(uint4*)(smem + OFF_BHI + b_st)      = pBh0;
        *(uint4*)(smem + OFF_BHI + b_st + 16) = pBh1;
        *(uint4*)(smem + OFF_BLO + b_st)      = pBl0;
        *(uint4*)(smem + OFF_BLO + b_st + 16) = pBl1;
    }
    __syncthreads();

    for (int kt = 0; kt < DIN / 32; kt++) {
        const uint32_t cb = (uint32_t)(kt & 1) * BUFB;

        if (kt < DIN / 32 - 1) {
            const float* ap = aptr + (kt + 1) * 32;
            pA0 = *(const float4*)(ap + 0);
            pA1 = *(const float4*)(ap + 4);
            const char* bh = (const char*)(bh_ptr + (kt + 1) * 32);
            const char* bl = (const char*)(bl_ptr + (kt + 1) * 32);
            pBh0 = *(const uint4*)(bh);
            pBh1 = *(const uint4*)(bh + 16);
            pBl0 = *(const uint4*)(bl);
            pBl1 = *(const uint4*)(bl + 16);
        }

        const uint32_t ahi_b = sb + cb + OFF_AHI;
        const uint32_t alo_b = sb + cb + OFF_ALO;
        const uint32_t bhi_b = sb + cb + OFF_BHI;
        const uint32_t blo_b = sb + cb + OFF_BLO;
        #pragma unroll
        for (int k16 = 0; k16 < 32; k16 += 16) {
            uint32_t ahi[2][4], alo[2][4];
            #pragma unroll
            for (int mi = 0; mi < 2; mi++) {
                const uint32_t a_off = (uint32_t)(warp_m + mi * 16 + a_r) * RPAD
                                     + (uint32_t)(k16 + a_cg * 8) * 2;
                LDSM_X4(ahi[mi][0], ahi[mi][1], ahi[mi][2], ahi[mi][3], ahi_b + a_off);
                LDSM_X4(alo[mi][0], alo[mi][1], alo[mi][2], alo[mi][3], alo_b + a_off);
            }
            #pragma unroll
            for (int g = 0; g < 4; g++) {
                const uint32_t b_off = (uint32_t)(warp_n + g * 16 + b_nn) * RPAD
                                     + (uint32_t)(k16 + b_kk) * 2;
                uint32_t bh[4], bl[4];
                LDSM_X4(bh[0], bh[1], bh[2], bh[3], bhi_b + b_off);
                LDSM_X4(bl[0], bl[1], bl[2], bl[3], blo_b + b_off);
                #pragma unroll
                for (int mi = 0; mi < 2; mi++) {
                    MMA16816(acc[mi][g * 2 + 0], ahi[mi], bh[0], bh[1]);
                    MMA16816(acc[mi][g * 2 + 1], ahi[mi], bh[2], bh[3]);
                    MMA16816(acc[mi][g * 2 + 0], alo[mi], bh[0], bh[1]);
                    MMA16816(acc[mi][g * 2 + 1], alo[mi], bh[2], bh[3]);
                    MMA16816(acc[mi][g * 2 + 0], ahi[mi], bl[0], bl[1]);
                    MMA16816(acc[mi][g * 2 + 1], ahi[mi], bl[2], bl[3]);
                }
            }
        }

        if (kt < DIN / 32 - 1) {
            const uint32_t nb = (uint32_t)((kt + 1) & 1) * BUFB;
            uint32_t h[4], l[4];
            split2(pA0.x, pA0.y, h[0], l[0]);
            split2(pA0.z, pA0.w, h[1], l[1]);
            split2(pA1.x, pA1.y, h[2], l[2]);
            split2(pA1.z, pA1.w, h[3], l[3]);
            *(uint4*)(smem + nb + OFF_AHI + a_st) = make_uint4(h[0], h[1], h[2], h[3]);
            *(uint4*)(smem + nb + OFF_ALO + a_st) = make_uint4(l[0], l[1], l[2], l[3]);
            *(uint4*)(smem + nb + OFF_BHI + b_st)      = pBh0;
            *(uint4*)(smem + nb + OFF_BHI + b_st + 16) = pBh1;
            *(uint4*)(smem + nb + OFF_BLO + b_st)      = pBl0;
            *(uint4*)(smem + nb + OFF_BLO + b_st + 16) = pBl1;
        }
        __syncthreads();
    }

    // ---- epilogue: acc -> smem h (stride HS) ----
    const int er = lane >> 2;
    const int ec = (lane & 3) * 2;
    #pragma unroll
    for (int mi = 0; mi < 2; mi++) {
        #pragma unroll
        for (int nf = 0; nf < 8; nf++) {
            int row = warp_m + mi * 16 + er;
            int col = warp_n + nf * 8 + ec;
            *(float2*)&sH[(size_t)row * HS + col] =
                make_float2(acc[mi][nf][0], acc[mi][nf][1]);
            *(float2*)&sH[(size_t)(row + 8) * HS + col] =
                make_float2(acc[mi][nf][2], acc[mi][nf][3]);
        }
    }
    __syncthreads();

    // ---- agg + PReLU + pool/anchor ----
    const int half = tid >> 8;
    const int col  = tid & 255;
    const int hw   = wid & 7;
    const float pa = prelu_a[0];
    const float bj = b_gcn[col];
    float poolv[8], anchv[8], vp[8], va[8];
    #pragma unroll
    for (int q = 0; q < 8; q++) {
        const int blk = half * 8 + q;
        float x[SS];
        #pragma unroll
        for (int s = 0; s < SS; s++) x[s] = sH[(size_t)(blk * 8 + s) * HS + col];
        float pool = 0.f, anchor = 0.f;
        #pragma unroll
        for (int r = 0; r < SS; r++) {
            float a = bj;
            #pragma unroll
            for (int s = 0; s < SS; s++)
                a = fmaf(sAdj[blk * 64 + r * 8 + s], x[s], a);
            float h = (a >= 0.f) ? a : pa * a;
            if (r < SS - 1) pool += h;
            else            anchor = h;
        }
        pool *= (1.0f / (float)(SS - 1));
        poolv[q] = pool;
        anchv[q] = anchor;
        float p2s = pool * pool, a2s = anchor * anchor;
        #pragma unroll
        for (int o = 16; o; o >>= 1) {
            p2s += __shfl_xor_sync(0xffffffffu, p2s, o);
            a2s += __shfl_xor_sync(0xffffffffu, a2s, o);
        }
        vp[q] = p2s;
        va[q] = a2s;
    }
    if (lane == 0) {
        #pragma unroll
        for (int q = 0; q < 8; q++) {
            const int blk = half * 8 + q;
            sRed[blk * 16 + hw * 2 + 0] = vp[q];
            sRed[blk * 16 + hw * 2 + 1] = va[q];
        }
    }
    __syncthreads();

    const int b0 = mloc / SS;
    #pragma unroll
    for (int q = 0; q < 8; q++) {
        const int blk = half * 8 + q;
        float sp = 0.f, sa = 0.f;
        #pragma unroll
        for (int w = 0; w < 8; w++) {
            sp += sRed[blk * 16 + w * 2 + 0];
            sa += sRed[blk * 16 + w * 2 + 1];
        }
        const float inp = 1.f / fmaxf(sqrtf(sp), 1e-12f);
        const float ina = 1.f / fmaxf(sqrtf(sa), 1e-12f);
        const size_t gi = (size_t)(b0 + blk) * DOUT + col;
        if (is_pos) {
            g_pos_pool[gi] = poolv[q] * inp;
            g_anchor[gi]   = anchv[q] * ina;
        } else {
            g_neg_pool[gi] = poolv[q] * inp;
        }
    }
}

// ====== GEMM2 via bf16 3-term mma + fused score, single wave (128 CTAs) ======
// T-tile = anchor[128 rows] @ W_bil^T over n-half 128, K=256. 256 threads,
// 8 warps (4m x 2n), warp tile 32x64. Epilogue: T -> smem, dot with pools,
// atomicAdd partial scores (out pre-initialized to b_bil).
#define TS 132    // T smem row stride (floats)
#define G2_AHI 0
#define G2_ALO 10240
#define G2_BHI 20480
#define G2_BLO 30720
#define G2_SMEM (128 * TS * 4)   // 67584; unions operand tiles (<= 40960)

__global__ __launch_bounds__(256, 1) void gemm2_mma(float* __restrict__ out)
{
    extern __shared__ __align__(16) char smem[];
    float* sT = (float*)smem;

    const int tid = threadIdx.x;
    const int wid = tid >> 5;
    const int lane = tid & 31;

    const int m0 = blockIdx.x * 128;
    const int n0 = blockIdx.y * 128;
    const int warp_m = (wid & 3) * 32;
    const int warp_n = (wid >> 2) * 64;

    const uint32_t sb = smem_u32(smem);

    // loaders: A anchor rows (fp32, split on the fly), 128 rows x 32 floats
    const int a_lrow = tid >> 1;                 // 0..127
    const int a_part = (tid & 1) * 16;           // 16 floats per thread
    const float* aptr = g_anchor + (size_t)(m0 + a_lrow) * DOUT + a_part;
    const uint32_t a_st = (uint32_t)a_lrow * RPAD + (uint32_t)a_part * 2;

    // B: W_bil rows n0+row (pre-split), 128 rows x 32 bf16
    const int b_lrow = tid >> 1;
    const int b_part = (tid & 1) * 16;
    const __nv_bfloat16* bh_ptr = g_wb_hi + (size_t)(n0 + b_lrow) * DOUT + b_part;
    const __nv_bfloat16* bl_ptr = g_wb_lo + (size_t)(n0 + b_lrow) * DOUT + b_part;
    const uint32_t b_st = (uint32_t)b_lrow * RPAD + (uint32_t)b_part * 2;

    const int a_r  = lane & 15;
    const int a_cg = lane >> 4;
    const int b_t  = lane >> 3;
    const int b_r  = lane & 7;
    const int b_nn = ((b_t >> 1) << 3) + b_r;
    const int b_kk = (b_t & 1) << 3;

    float acc[2][8][4];
    #pragma unroll
    for (int i = 0; i < 2; i++)
        #pragma unroll
        for (int j = 0; j < 8; j++)
            #pragma unroll
            for (int q = 0; q < 4; q++) acc[i][j][q] = 0.f;

    for (int kt = 0; kt < DOUT / 32; kt++) {
        const int k0 = kt * 32;
        {
            const float* ap = aptr + k0;
            float4 v0 = *(const float4*)(ap + 0);
            float4 v1 = *(const float4*)(ap + 4);
            float4 v2 = *(const float4*)(ap + 8);
            float4 v3 = *(const float4*)(ap + 12);
            uint32_t h[8], l[8];
            split2(v0.x, v0.y, h[0], l[0]);
            split2(v0.z, v0.w, h[1], l[1]);
            split2(v1.x, v1.y, h[2], l[2]);
            split2(v1.z, v1.w, h[3], l[3]);
            split2(v2.x, v2.y, h[4], l[4]);
            split2(v2.z, v2.w, h[5], l[5]);
            split2(v3.x, v3.y, h[6], l[6]);
            split2(v3.z, v3.w, h[7], l[7]);
            *(uint4*)(smem + G2_AHI + a_st)      = make_uint4(h[0], h[1], h[2], h[3]);
            *(uint4*)(smem + G2_AHI + a_st + 16) = make_uint4(h[4], h[5], h[6], h[7]);
            *(uint4*)(smem + G2_ALO + a_st)      = make_uint4(l[0], l[1], l[2], l[3]);
            *(uint4*)(smem + G2_ALO + a_st + 16) = make_uint4(l[4], l[5], l[6], l[7]);
        }
        {
            const char* bh = (const char*)(bh_ptr + k0);
            const char* bl = (const char*)(bl_ptr + k0);
            uint4 h0 = *(const uint4*)(bh);
            uint4 h1 = *(const uint4*)(bh + 16);
            uint4 l0 = *(const uint4*)(bl);
            uint4 l1 = *(const uint4*)(bl + 16);
            *(uint4*)(smem + G2_BHI + b_st)      = h0;
            *(uint4*)(smem + G2_BHI + b_st + 16) = h1;
            *(uint4*)(smem + G2_BLO + b_st)      = l0;
            *(uint4*)(smem + G2_BLO + b_st + 16) = l1;
        }
        __syncthreads();

        #pragma unroll
        for (int k16 = 0; k16 < 32; k16 += 16) {
            uint32_t ahi[2][4], alo[2][4];
            #pragma unroll
            for (int mi = 0; mi < 2; mi++) {
                const uint32_t a_off = (uint32_t)(warp_m + mi * 16 + a_r) * RPAD
                                     + (uint32_t)(k16 + a_cg * 8) * 2;
                LDSM_X4(ahi[mi][0], ahi[mi][1], ahi[mi][2], ahi[mi][3], sb + G2_AHI + a_off);
                LDSM_X4(alo[mi][0], alo[mi][1], alo[mi][2], alo[mi][3], sb + G2_ALO + a_off);
            }
            #pragma unroll
            for (int g = 0; g < 4; g++) {
                const uint32_t b_off = (uint32_t)(warp_n + g * 16 + b_nn) * RPAD
                                     + (uint32_t)(k16 + b_kk) * 2;
                uint32_t bh[4], bl[4];
                LDSM_X4(bh[0], bh[1], bh[2], bh[3], sb + G2_BHI + b_off);
                LDSM_X4(bl[0], bl[1], bl[2], bl[3], sb + G2_BLO + b_off);
                #pragma unroll
                for (int mi = 0; mi < 2; mi++) {
                    MMA16816(acc[mi][g * 2 + 0], ahi[mi], bh[0], bh[1]);
                    MMA16816(acc[mi][g * 2 + 1], ahi[mi], bh[2], bh[3]);
                    MMA16816(acc[mi][g * 2 + 0], alo[mi], bh[0], bh[1]);
                    MMA16816(acc[mi][g * 2 + 1], alo[mi], bh[2], bh[3]);
                    MMA16816(acc[mi][g * 2 + 0], ahi[mi], bl[0], bl[1]);
                    MMA16816(acc[mi][g * 2 + 1], ahi[mi], bl[2], bl[3]);
                }
            }
        }
        __syncthreads();
    }

    // ---- T tile -> smem ----
    const int er = lane >> 2;
    const int ec = (lane & 3) * 2;
    #pragma unroll
    for (int mi = 0; mi < 2; mi++) {
        #pragma unroll
        for (int nf = 0; nf < 8; nf++) {
            int row = warp_m + mi * 16 + er;
            int col = warp_n + nf * 8 + ec;
            *(float2*)&sT[(size_t)row * TS + col] =
                make_float2(acc[mi][nf][0], acc[mi][nf][1]);
            *(float2*)&sT[(size_t)(row + 8) * TS + col] =
                make_float2(acc[mi][nf][2], acc[mi][nf][3]);
        }
    }
    __syncthreads();

    // ---- fused score: warp w handles rows w*16..w*16+15 ----
    #pragma unroll
    for (int rr = 0; rr < 16; rr++) {
        const int r = wid * 16 + rr;
        const int grow = m0 + r;
        const float* pp = g_pos_pool + (size_t)grow * DOUT + n0;
        const float* np = g_neg_pool + (size_t)grow * DOUT + n0;
        float sp = 0.f, sn = 0.f;
        #pragma unroll
        for (int q = 0; q < 4; q++) {
            float t = sT[(size_t)r * TS + lane + q * 32];
            sp = fmaf(t, pp[lane + q * 32], sp);
            sn = fmaf(t, np[lane + q * 32], sn);
        }
        #pragma unroll
        for (int o = 16; o; o >>= 1) {
            sp += __shfl_xor_sync(0xffffffffu, sp, o);
            sn += __shfl_xor_sync(0xffffffffu, sn, o);
        }
        if (lane == 0) {
            atomicAdd(&out[grow], sp);
            atomicAdd(&out[NB + grow], sn);
        }
    }
}

extern "C" void kernel_launch(void* const* d_in, const int* in_sizes, int n_in,
                              void* d_out, int out_size)
{
    const float* pos_x   = (const float*)d_in[0];
    const float* neg_x   = (const float*)d_in[1];
    const int*   pos_src = (const int*)d_in[2];
    const int*   pos_dst = (const int*)d_in[3];
    const float* pos_w   = (const float*)d_in[4];
    const int*   neg_src = (const int*)d_in[5];
    const int*   neg_dst = (const int*)d_in[6];
    const float* neg_w   = (const float*)d_in[7];
    const float* W_gcn   = (const float*)d_in[8];
    const float* b_gcn   = (const float*)d_in[9];
    const float* prelu_a = (const float*)d_in[10];
    const float* W_bil   = (const float*)d_in[11];
    const float* b_bil   = (const float*)d_in[12];
    float* out = (float*)d_out;

    (void)in_sizes; (void)n_in; (void)out_size;

    cudaFuncSetAttribute(gemm1_fused, cudaFuncAttributeMaxDynamicSharedMemorySize,
                         SMEM_SZ);
    cudaFuncSetAttribute(gemm2_mma, cudaFuncAttributeMaxDynamicSharedMemorySize,
                         G2_SMEM);

    // 0) weight splits + out init
    wsplit_kernel<<<512, 256>>>(W_gcn);
    wsplit_bil_kernel<<<256, 256>>>(W_bil);
    out_init_kernel<<<2 * NB / 256, 256>>>(b_bil, out);

    // 1) fused: xw GEMM + agg + PReLU + pool + anchor + L2 norm
    gemm1_fused<<<2 * NNODES / 128, 512, SMEM_SZ>>>(
        pos_x, neg_x, pos_src, pos_dst, pos_w,
        neg_src, neg_dst, neg_w, b_gcn, prelu_a);

    // 2) T = anchor @ W_bil^T (bf16 3-term mma) + fused scores, single wave
    gemm2_mma<<<dim3(NB / 128, DOUT / 128), 256, G2_SMEM>>>(out);
}